// round 8
// baseline (speedup 1.0000x reference)
#include <cuda_runtime.h>
#include <cuda_fp16.h>
#include <cstdint>

#define NROWS 4096
#define KDIM  2048
#define MARGIN_F 0.3f

#define TM 128
#define TN 256
#define KC 64                        // f16 k-chunk: 128 bytes per row
#define NCHUNK (KDIM / KC)           // 32
#define NTHREADS 256                 // 8 warps, warp tile 64x64

#define A_BYTES (TM * KC * 2)        // 16384
#define B_BYTES (TN * KC * 2)        // 32768
#define STAGE_BYTES (A_BYTES + B_BYTES)   // 49152
#define NSTAGE 4
#define DYN_BYTES (NSTAGE * STAGE_BYTES + 1024)  // 197632

__device__ float  g_sq[NROWS];
__device__ int    g_ap[NROWS];   // d^2 bits (non-negative) -> int max/min valid
__device__ int    g_an[NROWS];
__device__ __half g_xh[NROWS * KDIM];   // fp16 copy of inputs (16 MB)

static __device__ __forceinline__ uint32_t smem_u32(const void* p) {
    uint32_t a;
    asm("{ .reg .u64 t; cvta.to.shared.u64 t, %1; cvt.u32.u64 %0, t; }" : "=r"(a) : "l"(p));
    return a;
}
static __device__ __forceinline__ void cp16(uint32_t s, const void* g) {
    asm volatile("cp.async.cg.shared.global [%0], [%1], 16;" :: "r"(s), "l"(g));
}
#define CP_COMMIT() asm volatile("cp.async.commit_group;" ::: "memory")
#define CP_WAIT2()  asm volatile("cp.async.wait_group 2;" ::: "memory")

static __device__ __forceinline__ void mma_f16(float* d, const uint32_t* a, const uint32_t* b) {
    asm volatile(
        "mma.sync.aligned.m16n8k16.row.col.f32.f16.f16.f32 "
        "{%0,%1,%2,%3}, {%4,%5,%6,%7}, {%8,%9}, {%0,%1,%2,%3};"
        : "+f"(d[0]), "+f"(d[1]), "+f"(d[2]), "+f"(d[3])
        : "r"(a[0]), "r"(a[1]), "r"(a[2]), "r"(a[3]), "r"(b[0]), "r"(b[1]));
}
static __device__ __forceinline__ void ldsm4(uint32_t* r, uint32_t addr) {
    asm volatile("ldmatrix.sync.aligned.m8n8.x4.shared.b16 {%0,%1,%2,%3}, [%4];"
        : "=r"(r[0]), "=r"(r[1]), "=r"(r[2]), "=r"(r[3]) : "r"(addr));
}

// ---------------------------------------------------------------------------
// Kernel 1: squared norms + init accumulators + fp16 copy of the input
// ---------------------------------------------------------------------------
__global__ void __launch_bounds__(256) prep_kernel(const float* __restrict__ x) {
    int row = blockIdx.x;
    const float4* xr = reinterpret_cast<const float4*>(x + (size_t)row * KDIM);
    uint2* xh = reinterpret_cast<uint2*>(g_xh + (size_t)row * KDIM);
    float s = 0.f;
    for (int i = threadIdx.x; i < KDIM / 4; i += 256) {
        float4 v = xr[i];
        s += v.x * v.x + v.y * v.y + v.z * v.z + v.w * v.w;
        __half2 h0 = __floats2half2_rn(v.x, v.y);
        __half2 h1 = __floats2half2_rn(v.z, v.w);
        uint2 hp;
        hp.x = *reinterpret_cast<uint32_t*>(&h0);
        hp.y = *reinterpret_cast<uint32_t*>(&h1);
        xh[i] = hp;
    }
    __shared__ float red[8];
    #pragma unroll
    for (int o = 16; o; o >>= 1) s += __shfl_down_sync(0xffffffffu, s, o);
    if ((threadIdx.x & 31) == 0) red[threadIdx.x >> 5] = s;
    __syncthreads();
    if (threadIdx.x == 0) {
        float t = 0.f;
        #pragma unroll
        for (int w = 0; w < 8; w++) t += red[w];
        g_sq[row] = t;
        g_ap[row] = 0;
        g_an[row] = 0x7f800000;
    }
}

// ---------------------------------------------------------------------------
// Kernel 2: fp16 mma.sync Gram tile (128x256), 8 warps of 64x64 (square warp
// tiles minimize smem crossbar re-reads: 131KB/chunk vs 196KB at 64x32).
// 4-stage cp.async issued before the MMA burst. Upper-triangle tiles only.
// ---------------------------------------------------------------------------
__global__ void __launch_bounds__(NTHREADS, 1)
dist_kernel(const int* __restrict__ tg) {
    int bi = blockIdx.y, bj = blockIdx.x;
    if (bj < (bi >> 1)) return;   // tile fully below diagonal

    extern __shared__ char raw_dsm[];
    __shared__ int   s_ap_r[TM], s_an_r[TM];
    __shared__ int   s_ap_c[TN], s_an_c[TN];
    __shared__ float s_sqi[TM],  s_sqj[TN];
    __shared__ int   s_li[TM],   s_lj[TN];

    int tid = threadIdx.x, lid = tid & 31, wid = tid >> 5;
    int wm = wid >> 2, wn = wid & 3;       // 2 x 4 warp grid, warp tile 64x64
    int u = lid >> 2, v = lid & 3;
    int r8 = lid & 7, mq = lid >> 3;       // ldmatrix lane decomposition
    int mlow = mq & 1, mhigh = mq >> 1;

    uint32_t raw_base = smem_u32(raw_dsm);
    uint32_t sbase = (raw_base + 1023u) & ~1023u;

    const __half* Ab = g_xh + (size_t)(bi * TM) * KDIM;
    const __half* Bb = g_xh + (size_t)(bj * TN) * KDIM;

    if (tid < TM) {
        s_ap_r[tid] = 0; s_an_r[tid] = 0x7f800000;
        s_sqi[tid] = g_sq[bi * TM + tid];
        s_li[tid]  = tg[bi * TM + tid];
    }
    {
        s_ap_c[tid] = 0; s_an_c[tid] = 0x7f800000;
        s_sqj[tid] = g_sq[bj * TN + tid];
        s_lj[tid]  = tg[bj * TN + tid];
    }

    float acc[4][8][4];
    #pragma unroll
    for (int mt = 0; mt < 4; mt++)
        #pragma unroll
        for (int nt = 0; nt < 8; nt++)
            #pragma unroll
            for (int q = 0; q < 4; q++) acc[mt][nt][q] = 0.f;

    // ldmatrix lane bases (proven R7 mapping, wn scaled to 64-wide tiles)
    uint32_t a_lane = (uint32_t)((wm * 64 + mlow * 8 + r8) * 128);
    uint32_t b_lane = (uint32_t)A_BYTES + (uint32_t)((wn * 64 + mhigh * 8 + r8) * 128);
    uint32_t akx[4], bkx[4];
    #pragma unroll
    for (int ks = 0; ks < 4; ks++) {
        akx[ks] = (uint32_t)((ks * 32 + mhigh * 16) ^ (r8 * 16));
        bkx[ks] = (uint32_t)((ks * 32 + mlow  * 16) ^ (r8 * 16));
    }

    // staging: f16 rows, 128B/row = 8 x 16B units; byte = r*128 + ((c4*16) ^ ((r&7)*16))
    #define STAGE(ic, s) do {                                                  \
        uint32_t b0_ = sbase + (uint32_t)(s) * STAGE_BYTES;                    \
        const __half* Ak_ = Ab + (ic) * KC;                                    \
        const __half* Bk_ = Bb + (ic) * KC;                                    \
        _Pragma("unroll")                                                      \
        for (int t = 0; t < 4; t++) {                                          \
            int idx = tid + t * NTHREADS; int r = idx >> 3, c4 = idx & 7;      \
            uint32_t sw = (uint32_t)(r * 128 + ((c4 * 16) ^ ((r & 7) * 16)));  \
            cp16(b0_ + sw, Ak_ + (size_t)r * KDIM + c4 * 8);                   \
        }                                                                      \
        _Pragma("unroll")                                                      \
        for (int t = 0; t < 8; t++) {                                          \
            int idx = tid + t * NTHREADS; int r = idx >> 3, c4 = idx & 7;      \
            uint32_t sw = (uint32_t)(r * 128 + ((c4 * 16) ^ ((r & 7) * 16)));  \
            cp16(b0_ + A_BYTES + sw, Bk_ + (size_t)r * KDIM + c4 * 8);         \
        }                                                                      \
    } while (0)

    STAGE(0, 0); CP_COMMIT();
    STAGE(1, 1); CP_COMMIT();
    STAGE(2, 2); CP_COMMIT();

    for (int ic = 0; ic < NCHUNK; ic++) {
        int s = ic & 3;
        CP_WAIT2();
        __syncthreads();   // all warps done reading stage (ic-1)&3 == (ic+3)&3

        // issue next stage's loads BEFORE the MMA burst (L2 head start)
        if (ic + 3 < NCHUNK) STAGE(ic + 3, (ic + 3) & 3);
        CP_COMMIT();

        uint32_t stg = sbase + (uint32_t)s * STAGE_BYTES;
        uint32_t a0 = stg + a_lane;
        uint32_t b0 = stg + b_lane;

        #pragma unroll
        for (int ks = 0; ks < 4; ks++) {
            uint32_t af[4][4], rb[4][4];
            #pragma unroll
            for (int mt = 0; mt < 4; mt++)
                ldsm4(af[mt], a0 + (uint32_t)(mt * 2048) + akx[ks]);
            #pragma unroll
            for (int np = 0; np < 4; np++)
                ldsm4(rb[np], b0 + (uint32_t)(np * 2048) + bkx[ks]);
            #pragma unroll
            for (int mt = 0; mt < 4; mt++) {
                #pragma unroll
                for (int np = 0; np < 4; np++) {
                    mma_f16(acc[mt][np * 2 + 0], af[mt], &rb[np][0]);
                    mma_f16(acc[mt][np * 2 + 1], af[mt], &rb[np][2]);
                }
            }
        }
    }

    // ---- epilogue: d^2, masked hardest pos/neg, idempotent reductions ----
    const float INF = __int_as_float(0x7f800000);
    float ap_r[8], an_r[8], ap_c[16], an_c[16];
    #pragma unroll
    for (int i = 0; i < 8; i++)  { ap_r[i] = 0.f; an_r[i] = INF; }
    #pragma unroll
    for (int i = 0; i < 16; i++) { ap_c[i] = 0.f; an_c[i] = INF; }

    #pragma unroll
    for (int mt = 0; mt < 4; mt++) {
        #pragma unroll
        for (int rh = 0; rh < 2; rh++) {
            int ml = wm * 64 + mt * 16 + u + rh * 8;
            float sqi = s_sqi[ml];
            int   li  = s_li[ml];
            int ri = mt * 2 + rh;
            float apv = ap_r[ri], anv = an_r[ri];
            #pragma unroll
            for (int nt = 0; nt < 8; nt++) {
                #pragma unroll
                for (int cb = 0; cb < 2; cb++) {
                    int nl = wn * 64 + nt * 8 + v * 2 + cb;
                    float d2 = fmaxf(fmaf(-2.f, acc[mt][nt][rh * 2 + cb],
                                          sqi + s_sqj[nl]), 0.f);
                    int ci = nt * 2 + cb;
                    if (li == s_lj[nl]) {
                        apv = fmaxf(apv, d2);
                        ap_c[ci] = fmaxf(ap_c[ci], d2);
                    } else {
                        anv = fminf(anv, d2);
                        an_c[ci] = fminf(an_c[ci], d2);
                    }
                }
            }
            ap_r[ri] = apv; an_r[ri] = anv;
        }
    }

    const unsigned FM = 0xffffffffu;
    #pragma unroll
    for (int i = 0; i < 8; i++) {          // reduce over v (4 col-lanes)
        float ap = ap_r[i], an = an_r[i];
        ap = fmaxf(ap, __shfl_xor_sync(FM, ap, 1));
        ap = fmaxf(ap, __shfl_xor_sync(FM, ap, 2));
        an = fminf(an, __shfl_xor_sync(FM, an, 1));
        an = fminf(an, __shfl_xor_sync(FM, an, 2));
        if (v == 0) {
            int ml = wm * 64 + (i >> 1) * 16 + u + (i & 1) * 8;
            atomicMax(&s_ap_r[ml], __float_as_int(ap));
            atomicMin(&s_an_r[ml], __float_as_int(an));
        }
    }
    #pragma unroll
    for (int i = 0; i < 16; i++) {         // reduce over u (8 row-lanes)
        float ap = ap_c[i], an = an_c[i];
        ap = fmaxf(ap, __shfl_xor_sync(FM, ap, 4));
        ap = fmaxf(ap, __shfl_xor_sync(FM, ap, 8));
        ap = fmaxf(ap, __shfl_xor_sync(FM, ap, 16));
        an = fminf(an, __shfl_xor_sync(FM, an, 4));
        an = fminf(an, __shfl_xor_sync(FM, an, 8));
        an = fminf(an, __shfl_xor_sync(FM, an, 16));
        if (u == 0) {
            int nl = wn * 64 + (i >> 1) * 8 + v * 2 + (i & 1);
            atomicMax(&s_ap_c[nl], __float_as_int(ap));
            atomicMin(&s_an_c[nl], __float_as_int(an));
        }
    }
    __syncthreads();

    if (tid < TM) {
        atomicMax(&g_ap[bi * TM + tid], s_ap_r[tid]);
        atomicMin(&g_an[bi * TM + tid], s_an_r[tid]);
    }
    {
        atomicMax(&g_ap[bj * TN + tid], s_ap_c[tid]);
        atomicMin(&g_an[bj * TN + tid], s_an_c[tid]);
    }
}

// ---------------------------------------------------------------------------
// Kernel 3: loss = mean(relu(margin + sqrt(ap2) - sqrt(an2)))
// ---------------------------------------------------------------------------
__global__ void __launch_bounds__(256) loss_kernel(float* __restrict__ out) {
    float s = 0.f;
    for (int i = threadIdx.x; i < NROWS; i += 256) {
        float ap = sqrtf(fmaxf(__int_as_float(g_ap[i]), 1e-12f));
        float an = sqrtf(fmaxf(__int_as_float(g_an[i]), 1e-12f));
        s += fmaxf(MARGIN_F + ap - an, 0.f);
    }
    __shared__ float red[8];
    #pragma unroll
    for (int o = 16; o; o >>= 1) s += __shfl_down_sync(0xffffffffu, s, o);
    if ((threadIdx.x & 31) == 0) red[threadIdx.x >> 5] = s;
    __syncthreads();
    if (threadIdx.x == 0) {
        float t = 0.f;
        #pragma unroll
        for (int w = 0; w < 8; w++) t += red[w];
        out[0] = t / (float)NROWS;
    }
}

extern "C" void kernel_launch(void* const* d_in, const int* in_sizes, int n_in,
                              void* d_out, int out_size) {
    const float* x  = (const float*)d_in[0];
    const int*   tg = (const int*)d_in[1];
    float* out = (float*)d_out;

    cudaFuncSetAttribute(dist_kernel, cudaFuncAttributeMaxDynamicSharedMemorySize, DYN_BYTES);

    prep_kernel<<<NROWS, 256>>>(x);
    dim3 grid(NROWS / TN, NROWS / TM);   // (16, 32): x=bj, y=bi
    dist_kernel<<<grid, NTHREADS, DYN_BYTES>>>(tg);
    loss_kernel<<<1, 256>>>(out);
}

// round 9
// speedup vs baseline: 1.0697x; 1.0697x over previous
#include <cuda_runtime.h>
#include <cuda_fp16.h>
#include <cstdint>

#define NROWS 4096
#define KDIM  2048
#define MARGIN_F 0.3f

#define TM 128
#define TN 256
#define KC 64                        // f16 k-chunk: 128 bytes per row
#define NCHUNK (KDIM / KC)           // 32
#define NTHREADS 512                 // 16 warps, warp tile 64x32 (R7 config)

#define A_BYTES (TM * KC * 2)        // 16384
#define B_BYTES (TN * KC * 2)        // 32768
#define STAGE_BYTES (A_BYTES + B_BYTES)   // 49152
#define NSTAGE 4
#define DYN_BYTES (NSTAGE * STAGE_BYTES + 1024)  // 197632

__device__ float  g_sq[NROWS];
__device__ int    g_ap[NROWS];   // d^2 bits (non-negative) -> int max/min valid
__device__ int    g_an[NROWS];
__device__ __half g_xh[NROWS * KDIM];   // fp16 copy of inputs (16 MB)

static __device__ __forceinline__ uint32_t smem_u32(const void* p) {
    uint32_t a;
    asm("{ .reg .u64 t; cvta.to.shared.u64 t, %1; cvt.u32.u64 %0, t; }" : "=r"(a) : "l"(p));
    return a;
}
static __device__ __forceinline__ void cp16(uint32_t s, const void* g) {
    asm volatile("cp.async.cg.shared.global [%0], [%1], 16;" :: "r"(s), "l"(g));
}
#define CP_COMMIT() asm volatile("cp.async.commit_group;" ::: "memory")
#define CP_WAIT2()  asm volatile("cp.async.wait_group 2;" ::: "memory")

static __device__ __forceinline__ void mma_f16(float* d, const uint32_t* a, const uint32_t* b) {
    asm volatile(
        "mma.sync.aligned.m16n8k16.row.col.f32.f16.f16.f32 "
        "{%0,%1,%2,%3}, {%4,%5,%6,%7}, {%8,%9}, {%0,%1,%2,%3};"
        : "+f"(d[0]), "+f"(d[1]), "+f"(d[2]), "+f"(d[3])
        : "r"(a[0]), "r"(a[1]), "r"(a[2]), "r"(a[3]), "r"(b[0]), "r"(b[1]));
}
static __device__ __forceinline__ void ldsm4(uint32_t* r, uint32_t addr) {
    asm volatile("ldmatrix.sync.aligned.m8n8.x4.shared.b16 {%0,%1,%2,%3}, [%4];"
        : "=r"(r[0]), "=r"(r[1]), "=r"(r[2]), "=r"(r[3]) : "r"(addr));
}

// ---------------------------------------------------------------------------
// Kernel 1: squared norms + init accumulators + fp16 copy. 2 rows per block
// (interleaved loads double per-thread MLP vs 1-row blocks).
// ---------------------------------------------------------------------------
__global__ void __launch_bounds__(256) prep_kernel(const float* __restrict__ x) {
    int row0 = blockIdx.x * 2;
    const float4* xr0 = reinterpret_cast<const float4*>(x + (size_t)row0 * KDIM);
    const float4* xr1 = reinterpret_cast<const float4*>(x + (size_t)(row0 + 1) * KDIM);
    uint2* xh0 = reinterpret_cast<uint2*>(g_xh + (size_t)row0 * KDIM);
    uint2* xh1 = reinterpret_cast<uint2*>(g_xh + (size_t)(row0 + 1) * KDIM);
    float s0 = 0.f, s1 = 0.f;
    #pragma unroll
    for (int t = 0; t < KDIM / 4 / 256; t++) {
        int i = threadIdx.x + t * 256;
        float4 v0 = xr0[i];
        float4 v1 = xr1[i];
        s0 += v0.x * v0.x + v0.y * v0.y + v0.z * v0.z + v0.w * v0.w;
        s1 += v1.x * v1.x + v1.y * v1.y + v1.z * v1.z + v1.w * v1.w;
        __half2 a0 = __floats2half2_rn(v0.x, v0.y), a1 = __floats2half2_rn(v0.z, v0.w);
        __half2 b0 = __floats2half2_rn(v1.x, v1.y), b1 = __floats2half2_rn(v1.z, v1.w);
        uint2 p0, p1;
        p0.x = *reinterpret_cast<uint32_t*>(&a0); p0.y = *reinterpret_cast<uint32_t*>(&a1);
        p1.x = *reinterpret_cast<uint32_t*>(&b0); p1.y = *reinterpret_cast<uint32_t*>(&b1);
        xh0[i] = p0;
        xh1[i] = p1;
    }
    __shared__ float red[16];
    #pragma unroll
    for (int o = 16; o; o >>= 1) {
        s0 += __shfl_down_sync(0xffffffffu, s0, o);
        s1 += __shfl_down_sync(0xffffffffu, s1, o);
    }
    if ((threadIdx.x & 31) == 0) {
        red[(threadIdx.x >> 5) * 2]     = s0;
        red[(threadIdx.x >> 5) * 2 + 1] = s1;
    }
    __syncthreads();
    if (threadIdx.x < 2) {
        float t = 0.f;
        #pragma unroll
        for (int w = 0; w < 8; w++) t += red[w * 2 + threadIdx.x];
        g_sq[row0 + threadIdx.x] = t;
        g_ap[row0 + threadIdx.x] = 0;
        g_an[row0 + threadIdx.x] = 0x7f800000;
    }
}

// ---------------------------------------------------------------------------
// Kernel 2: fp16 mma.sync Gram tile (128x256), 16 warps of 64x32, 4-stage
// cp.async issued before the MMA burst. Upper-triangle tiles only; epilogue
// compares d^2 (sqrt deferred), row- and col-side reductions.
// ---------------------------------------------------------------------------
__global__ void __launch_bounds__(NTHREADS, 1)
dist_kernel(const int* __restrict__ tg) {
    int bi = blockIdx.y, bj = blockIdx.x;
    if (bj < (bi >> 1)) return;   // tile fully below diagonal

    extern __shared__ char raw_dsm[];
    __shared__ int   s_ap_r[TM], s_an_r[TM];
    __shared__ int   s_ap_c[TN], s_an_c[TN];
    __shared__ float s_sqi[TM],  s_sqj[TN];
    __shared__ int   s_li[TM],   s_lj[TN];

    int tid = threadIdx.x, lid = tid & 31, wid = tid >> 5;
    int wm = wid >> 3, wn = wid & 7;       // 2 x 8 warp grid, warp tile 64x32
    int u = lid >> 2, v = lid & 3;
    int r8 = lid & 7, mq = lid >> 3;       // ldmatrix lane decomposition
    int mlow = mq & 1, mhigh = mq >> 1;

    uint32_t raw_base = smem_u32(raw_dsm);
    uint32_t sbase = (raw_base + 1023u) & ~1023u;

    const __half* Ab = g_xh + (size_t)(bi * TM) * KDIM;
    const __half* Bb = g_xh + (size_t)(bj * TN) * KDIM;

    if (tid < TM) {
        s_ap_r[tid] = 0; s_an_r[tid] = 0x7f800000;
        s_sqi[tid] = g_sq[bi * TM + tid];
        s_li[tid]  = tg[bi * TM + tid];
    }
    if (tid < TN) {
        s_ap_c[tid] = 0; s_an_c[tid] = 0x7f800000;
        s_sqj[tid] = g_sq[bj * TN + tid];
        s_lj[tid]  = tg[bj * TN + tid];
    }

    float acc[4][4][4];
    #pragma unroll
    for (int mt = 0; mt < 4; mt++)
        #pragma unroll
        for (int nt = 0; nt < 4; nt++)
            #pragma unroll
            for (int q = 0; q < 4; q++) acc[mt][nt][q] = 0.f;

    // ldmatrix lane bases: 128B rows (64 f16), 16B-unit XOR swizzle.
    uint32_t a_lane = (uint32_t)((wm * 64 + mlow * 8 + r8) * 128);
    uint32_t b_lane = (uint32_t)A_BYTES + (uint32_t)((wn * 32 + mhigh * 8 + r8) * 128);
    uint32_t akx[4], bkx[4];
    #pragma unroll
    for (int ks = 0; ks < 4; ks++) {
        akx[ks] = (uint32_t)((ks * 32 + mhigh * 16) ^ (r8 * 16));
        bkx[ks] = (uint32_t)((ks * 32 + mlow  * 16) ^ (r8 * 16));
    }

    // staging: f16 rows, 128B/row = 8 x 16B units; byte = r*128 + ((c4*16) ^ ((r&7)*16))
    #define STAGE(ic, s) do {                                                  \
        uint32_t b0_ = sbase + (uint32_t)(s) * STAGE_BYTES;                    \
        const __half* Ak_ = Ab + (ic) * KC;                                    \
        const __half* Bk_ = Bb + (ic) * KC;                                    \
        _Pragma("unroll")                                                      \
        for (int t = 0; t < 2; t++) {                                          \
            int idx = tid + t * NTHREADS; int r = idx >> 3, c4 = idx & 7;      \
            uint32_t sw = (uint32_t)(r * 128 + ((c4 * 16) ^ ((r & 7) * 16)));  \
            cp16(b0_ + sw, Ak_ + (size_t)r * KDIM + c4 * 8);                   \
        }                                                                      \
        _Pragma("unroll")                                                      \
        for (int t = 0; t < 4; t++) {                                          \
            int idx = tid + t * NTHREADS; int r = idx >> 3, c4 = idx & 7;      \
            uint32_t sw = (uint32_t)(r * 128 + ((c4 * 16) ^ ((r & 7) * 16)));  \
            cp16(b0_ + A_BYTES + sw, Bk_ + (size_t)r * KDIM + c4 * 8);         \
        }                                                                      \
    } while (0)

    STAGE(0, 0); CP_COMMIT();
    STAGE(1, 1); CP_COMMIT();
    STAGE(2, 2); CP_COMMIT();

    for (int ic = 0; ic < NCHUNK; ic++) {
        int s = ic & 3;
        CP_WAIT2();
        __syncthreads();   // all warps done reading stage (ic+3)&3 == (ic-1)&3

        // issue next stage's loads BEFORE the MMA burst (L2 head start)
        if (ic + 3 < NCHUNK) STAGE(ic + 3, (ic + 3) & 3);
        CP_COMMIT();

        uint32_t stg = sbase + (uint32_t)s * STAGE_BYTES;
        uint32_t a0 = stg + a_lane;
        uint32_t b0 = stg + b_lane;

        #pragma unroll
        for (int ks = 0; ks < 4; ks++) {
            uint32_t af[4][4], rb[2][4];
            #pragma unroll
            for (int mt = 0; mt < 4; mt++)
                ldsm4(af[mt], a0 + (uint32_t)(mt * 2048) + akx[ks]);
            #pragma unroll
            for (int ntp = 0; ntp < 2; ntp++)
                ldsm4(rb[ntp], b0 + (uint32_t)(ntp * 2048) + bkx[ks]);
            #pragma unroll
            for (int mt = 0; mt < 4; mt++) {
                #pragma unroll
                for (int ntp = 0; ntp < 2; ntp++) {
                    mma_f16(acc[mt][ntp * 2 + 0], af[mt], &rb[ntp][0]);
                    mma_f16(acc[mt][ntp * 2 + 1], af[mt], &rb[ntp][2]);
                }
            }
        }
    }

    // ---- epilogue: d^2, masked hardest pos/neg, idempotent reductions ----
    const float INF = __int_as_float(0x7f800000);
    float ap_r[8], an_r[8], ap_c[8], an_c[8];
    #pragma unroll
    for (int i = 0; i < 8; i++) { ap_r[i] = 0.f; an_r[i] = INF; ap_c[i] = 0.f; an_c[i] = INF; }

    #pragma unroll
    for (int mt = 0; mt < 4; mt++) {
        #pragma unroll
        for (int rh = 0; rh < 2; rh++) {
            int ml = wm * 64 + mt * 16 + u + rh * 8;
            float sqi = s_sqi[ml];
            int   li  = s_li[ml];
            int ri = mt * 2 + rh;
            float apv = ap_r[ri], anv = an_r[ri];
            #pragma unroll
            for (int nt = 0; nt < 4; nt++) {
                #pragma unroll
                for (int cb = 0; cb < 2; cb++) {
                    int nl = wn * 32 + nt * 8 + v * 2 + cb;
                    float d2 = fmaxf(fmaf(-2.f, acc[mt][nt][rh * 2 + cb],
                                          sqi + s_sqj[nl]), 0.f);
                    int ci = nt * 2 + cb;
                    if (li == s_lj[nl]) {
                        apv = fmaxf(apv, d2);
                        ap_c[ci] = fmaxf(ap_c[ci], d2);
                    } else {
                        anv = fminf(anv, d2);
                        an_c[ci] = fminf(an_c[ci], d2);
                    }
                }
            }
            ap_r[ri] = apv; an_r[ri] = anv;
        }
    }

    const unsigned FM = 0xffffffffu;
    #pragma unroll
    for (int i = 0; i < 8; i++) {          // reduce over v (4 col-lanes)
        float ap = ap_r[i], an = an_r[i];
        ap = fmaxf(ap, __shfl_xor_sync(FM, ap, 1));
        ap = fmaxf(ap, __shfl_xor_sync(FM, ap, 2));
        an = fminf(an, __shfl_xor_sync(FM, an, 1));
        an = fminf(an, __shfl_xor_sync(FM, an, 2));
        if (v == 0) {
            int ml = wm * 64 + (i >> 1) * 16 + u + (i & 1) * 8;
            atomicMax(&s_ap_r[ml], __float_as_int(ap));
            atomicMin(&s_an_r[ml], __float_as_int(an));
        }
    }
    #pragma unroll
    for (int i = 0; i < 8; i++) {          // reduce over u (8 row-lanes)
        float ap = ap_c[i], an = an_c[i];
        ap = fmaxf(ap, __shfl_xor_sync(FM, ap, 4));
        ap = fmaxf(ap, __shfl_xor_sync(FM, ap, 8));
        ap = fmaxf(ap, __shfl_xor_sync(FM, ap, 16));
        an = fminf(an, __shfl_xor_sync(FM, an, 4));
        an = fminf(an, __shfl_xor_sync(FM, an, 8));
        an = fminf(an, __shfl_xor_sync(FM, an, 16));
        if (u == 0) {
            int nl = wn * 32 + (i >> 1) * 8 + v * 2 + (i & 1);
            atomicMax(&s_ap_c[nl], __float_as_int(ap));
            atomicMin(&s_an_c[nl], __float_as_int(an));
        }
    }
    __syncthreads();

    if (tid < TM) {
        atomicMax(&g_ap[bi * TM + tid], s_ap_r[tid]);
        atomicMin(&g_an[bi * TM + tid], s_an_r[tid]);
    }
    if (tid < TN) {
        atomicMax(&g_ap[bj * TN + tid], s_ap_c[tid]);
        atomicMin(&g_an[bj * TN + tid], s_an_c[tid]);
    }
}

// ---------------------------------------------------------------------------
// Kernel 3: loss = mean(relu(margin + sqrt(ap2) - sqrt(an2)))
// ---------------------------------------------------------------------------
__global__ void __launch_bounds__(1024) loss_kernel(float* __restrict__ out) {
    float s = 0.f;
    for (int i = threadIdx.x; i < NROWS; i += 1024) {
        float ap = sqrtf(fmaxf(__int_as_float(g_ap[i]), 1e-12f));
        float an = sqrtf(fmaxf(__int_as_float(g_an[i]), 1e-12f));
        s += fmaxf(MARGIN_F + ap - an, 0.f);
    }
    __shared__ float red[32];
    #pragma unroll
    for (int o = 16; o; o >>= 1) s += __shfl_down_sync(0xffffffffu, s, o);
    if ((threadIdx.x & 31) == 0) red[threadIdx.x >> 5] = s;
    __syncthreads();
    if (threadIdx.x < 32) {
        float t = red[threadIdx.x];
        #pragma unroll
        for (int o = 16; o; o >>= 1) t += __shfl_down_sync(0xffffffffu, t, o);
        if (threadIdx.x == 0) out[0] = t / (float)NROWS;
    }
}

extern "C" void kernel_launch(void* const* d_in, const int* in_sizes, int n_in,
                              void* d_out, int out_size) {
    const float* x  = (const float*)d_in[0];
    const int*   tg = (const int*)d_in[1];
    float* out = (float*)d_out;

    cudaFuncSetAttribute(dist_kernel, cudaFuncAttributeMaxDynamicSharedMemorySize, DYN_BYTES);

    prep_kernel<<<NROWS / 2, 256>>>(x);
    dim3 grid(NROWS / TN, NROWS / TM);   // (16, 32): x=bj, y=bi
    dist_kernel<<<grid, NTHREADS, DYN_BYTES>>>(tg);
    loss_kernel<<<1, 1024>>>(out);
}

// round 10
// speedup vs baseline: 1.1549x; 1.0796x over previous
#include <cuda_runtime.h>
#include <cuda_fp16.h>
#include <cstdint>

#define NROWS 4096
#define KDIM  2048
#define MARGIN_F 0.3f

#define TM 128
#define TN 128
#define KC 64                        // f16 k-chunk: 128 bytes per row
#define NCHUNK (KDIM / KC)           // 32
#define NTHREADS 256                 // 8 warps, warp tile 64x32
#define NBT 32                       // 4096/128 block-tiles per side
#define NTILES (NBT * (NBT + 1) / 2) // 528 upper-tri tiles

#define A_BYTES (TM * KC * 2)        // 16384
#define B_BYTES (TN * KC * 2)        // 16384
#define STAGE_BYTES (A_BYTES + B_BYTES)   // 32768
#define NSTAGE 3
#define DYN_BYTES (NSTAGE * STAGE_BYTES + 1024)  // 99328

__device__ float  g_sq[NROWS];
__device__ int    g_ap[NROWS];   // d^2 bits (non-negative) -> int max/min valid
__device__ int    g_an[NROWS];
__device__ __half g_xh[NROWS * KDIM];   // fp16 copy of inputs (16 MB)

static __device__ __forceinline__ uint32_t smem_u32(const void* p) {
    uint32_t a;
    asm("{ .reg .u64 t; cvta.to.shared.u64 t, %1; cvt.u32.u64 %0, t; }" : "=r"(a) : "l"(p));
    return a;
}
static __device__ __forceinline__ void cp16(uint32_t s, const void* g) {
    asm volatile("cp.async.cg.shared.global [%0], [%1], 16;" :: "r"(s), "l"(g));
}
#define CP_COMMIT() asm volatile("cp.async.commit_group;" ::: "memory")
#define CP_WAIT1()  asm volatile("cp.async.wait_group 1;" ::: "memory")

static __device__ __forceinline__ void mma_f16(float* d, const uint32_t* a, const uint32_t* b) {
    asm volatile(
        "mma.sync.aligned.m16n8k16.row.col.f32.f16.f16.f32 "
        "{%0,%1,%2,%3}, {%4,%5,%6,%7}, {%8,%9}, {%0,%1,%2,%3};"
        : "+f"(d[0]), "+f"(d[1]), "+f"(d[2]), "+f"(d[3])
        : "r"(a[0]), "r"(a[1]), "r"(a[2]), "r"(a[3]), "r"(b[0]), "r"(b[1]));
}
static __device__ __forceinline__ void ldsm4(uint32_t* r, uint32_t addr) {
    asm volatile("ldmatrix.sync.aligned.m8n8.x4.shared.b16 {%0,%1,%2,%3}, [%4];"
        : "=r"(r[0]), "=r"(r[1]), "=r"(r[2]), "=r"(r[3]) : "r"(addr));
}

// ---------------------------------------------------------------------------
// Kernel 1: squared norms + init accumulators + fp16 copy (2 rows / block)
// ---------------------------------------------------------------------------
__global__ void __launch_bounds__(256) prep_kernel(const float* __restrict__ x) {
    int row0 = blockIdx.x * 2;
    const float4* xr0 = reinterpret_cast<const float4*>(x + (size_t)row0 * KDIM);
    const float4* xr1 = reinterpret_cast<const float4*>(x + (size_t)(row0 + 1) * KDIM);
    uint2* xh0 = reinterpret_cast<uint2*>(g_xh + (size_t)row0 * KDIM);
    uint2* xh1 = reinterpret_cast<uint2*>(g_xh + (size_t)(row0 + 1) * KDIM);
    float s0 = 0.f, s1 = 0.f;
    #pragma unroll
    for (int t = 0; t < KDIM / 4 / 256; t++) {
        int i = threadIdx.x + t * 256;
        float4 v0 = xr0[i];
        float4 v1 = xr1[i];
        s0 += v0.x * v0.x + v0.y * v0.y + v0.z * v0.z + v0.w * v0.w;
        s1 += v1.x * v1.x + v1.y * v1.y + v1.z * v1.z + v1.w * v1.w;
        __half2 a0 = __floats2half2_rn(v0.x, v0.y), a1 = __floats2half2_rn(v0.z, v0.w);
        __half2 b0 = __floats2half2_rn(v1.x, v1.y), b1 = __floats2half2_rn(v1.z, v1.w);
        uint2 p0, p1;
        p0.x = *reinterpret_cast<uint32_t*>(&a0); p0.y = *reinterpret_cast<uint32_t*>(&a1);
        p1.x = *reinterpret_cast<uint32_t*>(&b0); p1.y = *reinterpret_cast<uint32_t*>(&b1);
        xh0[i] = p0;
        xh1[i] = p1;
    }
    __shared__ float red[16];
    #pragma unroll
    for (int o = 16; o; o >>= 1) {
        s0 += __shfl_down_sync(0xffffffffu, s0, o);
        s1 += __shfl_down_sync(0xffffffffu, s1, o);
    }
    if ((threadIdx.x & 31) == 0) {
        red[(threadIdx.x >> 5) * 2]     = s0;
        red[(threadIdx.x >> 5) * 2 + 1] = s1;
    }
    __syncthreads();
    if (threadIdx.x < 2) {
        float t = 0.f;
        #pragma unroll
        for (int w = 0; w < 8; w++) t += red[w * 2 + threadIdx.x];
        g_sq[row0 + threadIdx.x] = t;
        g_ap[row0 + threadIdx.x] = 0;
        g_an[row0 + threadIdx.x] = 0x7f800000;
    }
}

// ---------------------------------------------------------------------------
// Kernel 2: fp16 mma.sync Gram tile (128x128), 8 warps of 64x32, 3-stage
// cp.async, 2 CTAs/SM (bubble hiding). Flat triangular grid (528 CTAs, no
// dead blocks). Epilogue on d^2, row- and col-side idempotent reductions.
// ---------------------------------------------------------------------------
__global__ void __launch_bounds__(NTHREADS, 2)
dist_kernel(const int* __restrict__ tg) {
    // decode flat tile index -> (bi, bj), bj >= bi
    int tix = blockIdx.x;
    int bi = (int)((65.0f - sqrtf(4225.0f - 8.0f * (float)tix)) * 0.5f);
    while (bi * (65 - bi) / 2 > tix) bi--;
    while ((bi + 1) * (64 - bi) / 2 <= tix) bi++;
    int bj = bi + (tix - bi * (65 - bi) / 2);

    extern __shared__ char raw_dsm[];
    __shared__ int   s_ap_r[TM], s_an_r[TM];
    __shared__ int   s_ap_c[TN], s_an_c[TN];
    __shared__ float s_sqi[TM],  s_sqj[TN];
    __shared__ int   s_li[TM],   s_lj[TN];

    int tid = threadIdx.x, lid = tid & 31, wid = tid >> 5;
    int wm = wid >> 2, wn = wid & 3;       // 2 x 4 warp grid, warp tile 64x32
    int u = lid >> 2, v = lid & 3;
    int r8 = lid & 7, mq = lid >> 3;       // ldmatrix lane decomposition
    int mlow = mq & 1, mhigh = mq >> 1;

    uint32_t raw_base = smem_u32(raw_dsm);
    uint32_t sbase = (raw_base + 1023u) & ~1023u;

    const __half* Ab = g_xh + (size_t)(bi * TM) * KDIM;
    const __half* Bb = g_xh + (size_t)(bj * TN) * KDIM;

    if (tid < TM) {
        s_ap_r[tid] = 0; s_an_r[tid] = 0x7f800000;
        s_sqi[tid] = g_sq[bi * TM + tid];
        s_li[tid]  = tg[bi * TM + tid];
        s_ap_c[tid] = 0; s_an_c[tid] = 0x7f800000;
        s_sqj[tid] = g_sq[bj * TN + tid];
        s_lj[tid]  = tg[bj * TN + tid];
    }

    float acc[4][4][4];
    #pragma unroll
    for (int mt = 0; mt < 4; mt++)
        #pragma unroll
        for (int nt = 0; nt < 4; nt++)
            #pragma unroll
            for (int q = 0; q < 4; q++) acc[mt][nt][q] = 0.f;

    // ldmatrix lane bases: 128B rows (64 f16), 16B-unit XOR swizzle.
    uint32_t a_lane = (uint32_t)((wm * 64 + mlow * 8 + r8) * 128);
    uint32_t b_lane = (uint32_t)A_BYTES + (uint32_t)((wn * 32 + mhigh * 8 + r8) * 128);
    uint32_t akx[4], bkx[4];
    #pragma unroll
    for (int ks = 0; ks < 4; ks++) {
        akx[ks] = (uint32_t)((ks * 32 + mhigh * 16) ^ (r8 * 16));
        bkx[ks] = (uint32_t)((ks * 32 + mlow  * 16) ^ (r8 * 16));
    }

    // staging: 128 rows x 8 16B-units each for A and B
    #define STAGE(ic, s) do {                                                  \
        uint32_t b0_ = sbase + (uint32_t)(s) * STAGE_BYTES;                    \
        const __half* Ak_ = Ab + (ic) * KC;                                    \
        const __half* Bk_ = Bb + (ic) * KC;                                    \
        _Pragma("unroll")                                                      \
        for (int t = 0; t < 4; t++) {                                          \
            int idx = tid + t * NTHREADS; int r = idx >> 3, c4 = idx & 7;      \
            uint32_t sw = (uint32_t)(r * 128 + ((c4 * 16) ^ ((r & 7) * 16)));  \
            cp16(b0_ + sw, Ak_ + (size_t)r * KDIM + c4 * 8);                   \
        }                                                                      \
        _Pragma("unroll")                                                      \
        for (int t = 0; t < 4; t++) {                                          \
            int idx = tid + t * NTHREADS; int r = idx >> 3, c4 = idx & 7;      \
            uint32_t sw = (uint32_t)(r * 128 + ((c4 * 16) ^ ((r & 7) * 16)));  \
            cp16(b0_ + A_BYTES + sw, Bk_ + (size_t)r * KDIM + c4 * 8);         \
        }                                                                      \
    } while (0)

    STAGE(0, 0); CP_COMMIT();
    STAGE(1, 1); CP_COMMIT();

    int snext = 2;
    for (int ic = 0; ic < NCHUNK; ic++) {
        CP_WAIT1();
        __syncthreads();   // stage ic ready; slot snext was fully read in ic-1

        if (ic + 2 < NCHUNK) { STAGE(ic + 2, snext); }
        CP_COMMIT();

        int s = snext + 1; if (s >= NSTAGE) s -= NSTAGE;   // = ic % 3
        snext = s;

        uint32_t stg = sbase + (uint32_t)s * STAGE_BYTES;
        uint32_t a0 = stg + a_lane;
        uint32_t b0 = stg + b_lane;

        #pragma unroll
        for (int ks = 0; ks < 4; ks++) {
            uint32_t af[4][4], rb[2][4];
            #pragma unroll
            for (int mt = 0; mt < 4; mt++)
                ldsm4(af[mt], a0 + (uint32_t)(mt * 2048) + akx[ks]);
            #pragma unroll
            for (int ntp = 0; ntp < 2; ntp++)
                ldsm4(rb[ntp], b0 + (uint32_t)(ntp * 2048) + bkx[ks]);
            #pragma unroll
            for (int mt = 0; mt < 4; mt++) {
                #pragma unroll
                for (int ntp = 0; ntp < 2; ntp++) {
                    mma_f16(acc[mt][ntp * 2 + 0], af[mt], &rb[ntp][0]);
                    mma_f16(acc[mt][ntp * 2 + 1], af[mt], &rb[ntp][2]);
                }
            }
        }
    }

    // ---- epilogue: d^2, masked hardest pos/neg, idempotent reductions ----
    const float INF = __int_as_float(0x7f800000);
    float ap_r[8], an_r[8], ap_c[8], an_c[8];
    #pragma unroll
    for (int i = 0; i < 8; i++) { ap_r[i] = 0.f; an_r[i] = INF; ap_c[i] = 0.f; an_c[i] = INF; }

    #pragma unroll
    for (int mt = 0; mt < 4; mt++) {
        #pragma unroll
        for (int rh = 0; rh < 2; rh++) {
            int ml = wm * 64 + mt * 16 + u + rh * 8;
            float sqi = s_sqi[ml];
            int   li  = s_li[ml];
            int ri = mt * 2 + rh;
            float apv = ap_r[ri], anv = an_r[ri];
            #pragma unroll
            for (int nt = 0; nt < 4; nt++) {
                #pragma unroll
                for (int cb = 0; cb < 2; cb++) {
                    int nl = wn * 32 + nt * 8 + v * 2 + cb;
                    float d2 = fmaxf(fmaf(-2.f, acc[mt][nt][rh * 2 + cb],
                                          sqi + s_sqj[nl]), 0.f);
                    int ci = nt * 2 + cb;
                    if (li == s_lj[nl]) {
                        apv = fmaxf(apv, d2);
                        ap_c[ci] = fmaxf(ap_c[ci], d2);
                    } else {
                        anv = fminf(anv, d2);
                        an_c[ci] = fminf(an_c[ci], d2);
                    }
                }
            }
            ap_r[ri] = apv; an_r[ri] = anv;
        }
    }

    const unsigned FM = 0xffffffffu;
    #pragma unroll
    for (int i = 0; i < 8; i++) {          // reduce over v (4 col-lanes)
        float ap = ap_r[i], an = an_r[i];
        ap = fmaxf(ap, __shfl_xor_sync(FM, ap, 1));
        ap = fmaxf(ap, __shfl_xor_sync(FM, ap, 2));
        an = fminf(an, __shfl_xor_sync(FM, an, 1));
        an = fminf(an, __shfl_xor_sync(FM, an, 2));
        if (v == 0) {
            int ml = wm * 64 + (i >> 1) * 16 + u + (i & 1) * 8;
            atomicMax(&s_ap_r[ml], __float_as_int(ap));
            atomicMin(&s_an_r[ml], __float_as_int(an));
        }
    }
    #pragma unroll
    for (int i = 0; i < 8; i++) {          // reduce over u (8 row-lanes)
        float ap = ap_c[i], an = an_c[i];
        ap = fmaxf(ap, __shfl_xor_sync(FM, ap, 4));
        ap = fmaxf(ap, __shfl_xor_sync(FM, ap, 8));
        ap = fmaxf(ap, __shfl_xor_sync(FM, ap, 16));
        an = fminf(an, __shfl_xor_sync(FM, an, 4));
        an = fminf(an, __shfl_xor_sync(FM, an, 8));
        an = fminf(an, __shfl_xor_sync(FM, an, 16));
        if (u == 0) {
            int nl = wn * 32 + (i >> 1) * 8 + v * 2 + (i & 1);
            atomicMax(&s_ap_c[nl], __float_as_int(ap));
            atomicMin(&s_an_c[nl], __float_as_int(an));
        }
    }
    __syncthreads();

    if (tid < TM) {
        atomicMax(&g_ap[bi * TM + tid], s_ap_r[tid]);
        atomicMin(&g_an[bi * TM + tid], s_an_r[tid]);
        atomicMax(&g_ap[bj * TN + tid], s_ap_c[tid]);
        atomicMin(&g_an[bj * TN + tid], s_an_c[tid]);
    }
}

// ---------------------------------------------------------------------------
// Kernel 3: loss = mean(relu(margin + sqrt(ap2) - sqrt(an2)))
// ---------------------------------------------------------------------------
__global__ void __launch_bounds__(1024) loss_kernel(float* __restrict__ out) {
    float s = 0.f;
    for (int i = threadIdx.x; i < NROWS; i += 1024) {
        float ap = sqrtf(fmaxf(__int_as_float(g_ap[i]), 1e-12f));
        float an = sqrtf(fmaxf(__int_as_float(g_an[i]), 1e-12f));
        s += fmaxf(MARGIN_F + ap - an, 0.f);
    }
    __shared__ float red[32];
    #pragma unroll
    for (int o = 16; o; o >>= 1) s += __shfl_down_sync(0xffffffffu, s, o);
    if ((threadIdx.x & 31) == 0) red[threadIdx.x >> 5] = s;
    __syncthreads();
    if (threadIdx.x < 32) {
        float t = red[threadIdx.x];
        #pragma unroll
        for (int o = 16; o; o >>= 1) t += __shfl_down_sync(0xffffffffu, t, o);
        if (threadIdx.x == 0) out[0] = t / (float)NROWS;
    }
}

extern "C" void kernel_launch(void* const* d_in, const int* in_sizes, int n_in,
                              void* d_out, int out_size) {
    const float* x  = (const float*)d_in[0];
    const int*   tg = (const int*)d_in[1];
    float* out = (float*)d_out;

    cudaFuncSetAttribute(dist_kernel, cudaFuncAttributeMaxDynamicSharedMemorySize, DYN_BYTES);

    prep_kernel<<<NROWS / 2, 256>>>(x);
    dist_kernel<<<NTILES, NTHREADS, DYN_BYTES>>>(tg);
    loss_kernel<<<1, 1024>>>(out);
}